// round 9
// baseline (speedup 1.0000x reference)
#include <cuda_runtime.h>
#include <math.h>

// Moebius transform on 3-D blocks + log|det J| row reduction.
// One CTA per batch row (grid=8192, 256 threads). Global traffic is staged
// through shared memory so every LDG.128/STG.128 is lane-contiguous
// (512B/warp/instr, 4 full 128B lines) instead of the 48B-lane-stride
// pattern (12 partial lines/instr). Threads read their 12 consecutive
// floats from smem (stride-12-word LDS.128: conflicting lanes are 8 apart,
// i.e. in different 8-lane phases -> conflict-free).
// Determinant via conformal-map closed form: |det J| = c^2 * |yn . Hn|,
// c = (1-|w|^2)/|n+w|^2, Hn = n - 2 p (n.p)/|p|^2 (Householder image of n).

__device__ __forceinline__ float fast_rcp(float a) {
    float r;
    asm("rcp.approx.f32 %0, %1;" : "=f"(r) : "f"(a));
    return r;
}

__device__ __forceinline__ float moebius_block3(
    float a0, float a1, float a2,     // x block
    float v0, float v1, float v2,     // w block
    float& y0, float& y1, float& y2)  // y block out
{
    // radial normalization
    float xns   = fmaf(a0, a0, fmaf(a1, a1, a2 * a2));
    float inv   = rsqrtf(xns);
    float xnorm = xns * inv;                 // sqrt(xns)

    float n0 = a0 * inv, n1 = a1 * inv, n2 = a2 * inv;
    float p0 = n0 + v0,  p1 = n1 + v1,  p2 = n2 + v2;   // n + w

    float wns  = fmaf(v0, v0, fmaf(v1, v1, v2 * v2));
    float pns  = fmaf(p0, p0, fmaf(p1, p1, p2 * p2));
    float invp = fast_rcp(pns);
    float c    = (1.0f - wns) * invp;

    float yn0 = fmaf(c, p0, v0);
    float yn1 = fmaf(c, p1, v1);
    float yn2 = fmaf(c, p2, v2);

    y0 = xnorm * yn0;
    y1 = xnorm * yn1;
    y2 = xnorm * yn2;

    // |det J| = c^2 * | yn . (n - 2 p (n.p)/|p|^2) |
    float np = fmaf(n0, p0, fmaf(n1, p1, n2 * p2));
    float t  = 2.0f * np * invp;
    float h0 = fmaf(-t, p0, n0);
    float h1 = fmaf(-t, p1, n1);
    float h2 = fmaf(-t, p2, n2);
    float d  = fmaf(yn0, h0, fmaf(yn1, h1, yn2 * h2));

    return c * c * fabsf(d);
}

// F = 3072 floats/row = 768 float4; 256 threads x 3 float4 each.
#define NV4 768

__global__ void __launch_bounds__(256)
moebius_kernel(const float* __restrict__ x,
               const float* __restrict__ w,
               float* __restrict__ y,
               float* __restrict__ logdet)
{
    __shared__ float4 sx[NV4];
    __shared__ float4 sw[NV4];
    __shared__ float4 sy[NV4];
    __shared__ float  ssum[8];

    const int row  = blockIdx.x;
    const int t    = threadIdx.x;
    const int lane = t & 31;
    const int warp = t >> 5;

    const float4* xg = reinterpret_cast<const float4*>(x) + (size_t)row * NV4;
    const float4* wg = reinterpret_cast<const float4*>(w) + (size_t)row * NV4;

    // Coalesced stage-in: 6 independent LDG.128 front-batched, then STS.
    float4 lx0 = xg[t],       lx1 = xg[t + 256], lx2 = xg[t + 512];
    float4 lw0 = wg[t],       lw1 = wg[t + 256], lw2 = wg[t + 512];
    sx[t] = lx0;  sx[t + 256] = lx1;  sx[t + 512] = lx2;
    sw[t] = lw0;  sw[t + 256] = lw1;  sw[t + 512] = lw2;
    __syncthreads();

    // Each thread's 12 consecutive floats = float4 indices 3t, 3t+1, 3t+2.
    float4 xa = sx[3*t], xb = sx[3*t + 1], xc = sx[3*t + 2];
    float4 wa = sw[3*t], wb = sw[3*t + 1], wc = sw[3*t + 2];

    float ys[12];
    float prod, pk;

    prod  = moebius_block3(xa.x, xa.y, xa.z, wa.x, wa.y, wa.z,
                           ys[0], ys[1], ys[2]);
    pk    = moebius_block3(xa.w, xb.x, xb.y, wa.w, wb.x, wb.y,
                           ys[3], ys[4], ys[5]);
    prod *= pk;
    pk    = moebius_block3(xb.z, xb.w, xc.x, wb.z, wb.w, wc.x,
                           ys[6], ys[7], ys[8]);
    prod *= pk;
    pk    = moebius_block3(xc.y, xc.z, xc.w, wc.y, wc.z, wc.w,
                           ys[9], ys[10], ys[11]);
    prod *= pk;

    sy[3*t]     = make_float4(ys[0], ys[1], ys[2],  ys[3]);
    sy[3*t + 1] = make_float4(ys[4], ys[5], ys[6],  ys[7]);
    sy[3*t + 2] = make_float4(ys[8], ys[9], ys[10], ys[11]);

    // log of product of the 4 |det|s; warp reduce; park partial in smem
    // before the same barrier that guards sy.
    float acc = __logf(prod);
#pragma unroll
    for (int o = 16; o > 0; o >>= 1)
        acc += __shfl_xor_sync(0xffffffffu, acc, o);
    if (lane == 0) ssum[warp] = acc;

    __syncthreads();

    // Coalesced stage-out (evict-first: pure write stream, no reuse).
    float4* yg = reinterpret_cast<float4*>(y) + (size_t)row * NV4;
    __stcs(yg + t,       sy[t]);
    __stcs(yg + t + 256, sy[t + 256]);
    __stcs(yg + t + 512, sy[t + 512]);

    if (warp == 0) {
        float s = (lane < 8) ? ssum[lane] : 0.0f;
#pragma unroll
        for (int o = 4; o > 0; o >>= 1)
            s += __shfl_xor_sync(0xffffffffu, s, o);
        if (lane == 0) logdet[row] = s;
    }
}

extern "C" void kernel_launch(void* const* d_in, const int* in_sizes, int n_in,
                              void* d_out, int out_size)
{
    const float* x = (const float*)d_in[0];
    const float* w = (const float*)d_in[1];
    float* out = (float*)d_out;

    const int total = in_sizes[0];          // B * F
    const int batch = out_size - total;     // out = y (B*F) ++ logdet (B)

    float* y      = out;
    float* logdet = out + (size_t)total;

    moebius_kernel<<<batch, 256>>>(x, w, y, logdet);
}

// round 10
// speedup vs baseline: 1.1782x; 1.1782x over previous
#include <cuda_runtime.h>
#include <math.h>

// Moebius transform on 3-D blocks + log|det J| row reduction.
// Two independent rows per 512-thread CTA (grid = batch/2): halves CTA
// scheduler churn vs one-row CTAs. Threads 0-255 own row 2*cta, threads
// 256-511 own row 2*cta+1. Each half reduces its own log-det with its own
// named barrier (bar.sync 1/2, 256) so the halves never couple — row B's
// load front overlaps row A's reduction tail.
// Per half: thread t handles floats [t*12, t*12+12) = 4 blocks of 3,
// all float4-coalesced.
// Determinant via conformal-map closed form: |det J| = c^2 * |yn . Hn|,
// c = (1-|w|^2)/|n+w|^2, Hn = n - 2 p (n.p)/|p|^2 (Householder image of n).

__device__ __forceinline__ float fast_rcp(float a) {
    float r;
    asm("rcp.approx.f32 %0, %1;" : "=f"(r) : "f"(a));
    return r;
}

__device__ __forceinline__ float moebius_block3(
    float a0, float a1, float a2,     // x block
    float v0, float v1, float v2,     // w block
    float& y0, float& y1, float& y2)  // y block out
{
    // radial normalization
    float xns   = fmaf(a0, a0, fmaf(a1, a1, a2 * a2));
    float inv   = rsqrtf(xns);
    float xnorm = xns * inv;                 // sqrt(xns)

    float n0 = a0 * inv, n1 = a1 * inv, n2 = a2 * inv;
    float p0 = n0 + v0,  p1 = n1 + v1,  p2 = n2 + v2;   // n + w

    float wns  = fmaf(v0, v0, fmaf(v1, v1, v2 * v2));
    float pns  = fmaf(p0, p0, fmaf(p1, p1, p2 * p2));
    float invp = fast_rcp(pns);
    float c    = (1.0f - wns) * invp;

    float yn0 = fmaf(c, p0, v0);
    float yn1 = fmaf(c, p1, v1);
    float yn2 = fmaf(c, p2, v2);

    y0 = xnorm * yn0;
    y1 = xnorm * yn1;
    y2 = xnorm * yn2;

    // |det J| = c^2 * | yn . (n - 2 p (n.p)/|p|^2) |
    float np = fmaf(n0, p0, fmaf(n1, p1, n2 * p2));
    float t  = 2.0f * np * invp;
    float h0 = fmaf(-t, p0, n0);
    float h1 = fmaf(-t, p1, n1);
    float h2 = fmaf(-t, p2, n2);
    float d  = fmaf(yn0, h0, fmaf(yn1, h1, yn2 * h2));

    return c * c * fabsf(d);
}

__global__ void __launch_bounds__(512)
moebius_kernel(const float* __restrict__ x,
               const float* __restrict__ w,
               float* __restrict__ y,
               float* __restrict__ logdet,
               int F)
{
    const int tid  = threadIdx.x;
    const int half = tid >> 8;                   // 0 or 1: which row
    const int t    = tid & 255;                  // thread within the row
    const int row  = blockIdx.x * 2 + half;
    const int base = row * F + t * 12;           // B*F < 2^31, fits int

    // 3x float4 loads of x and w each (12 floats = 4 blocks of 3)
    const float4* xv = reinterpret_cast<const float4*>(x + base);
    const float4* wv = reinterpret_cast<const float4*>(w + base);
    float4 xa = xv[0], xb = xv[1], xc = xv[2];
    float4 wa = wv[0], wb = wv[1], wc = wv[2];

    float ys[12];
    float prod, pk;

    prod  = moebius_block3(xa.x, xa.y, xa.z, wa.x, wa.y, wa.z,
                           ys[0], ys[1], ys[2]);
    pk    = moebius_block3(xa.w, xb.x, xb.y, wa.w, wb.x, wb.y,
                           ys[3], ys[4], ys[5]);
    prod *= pk;
    pk    = moebius_block3(xb.z, xb.w, xc.x, wb.z, wb.w, wc.x,
                           ys[6], ys[7], ys[8]);
    prod *= pk;
    pk    = moebius_block3(xc.y, xc.z, xc.w, wc.y, wc.z, wc.w,
                           ys[9], ys[10], ys[11]);
    prod *= pk;

    float4* yv = reinterpret_cast<float4*>(y + base);
    __stcs(yv + 0, make_float4(ys[0], ys[1], ys[2],  ys[3]));
    __stcs(yv + 1, make_float4(ys[4], ys[5], ys[6],  ys[7]));
    __stcs(yv + 2, make_float4(ys[8], ys[9], ys[10], ys[11]));

    // log of product of the 4 |det|s: one fast log per thread
    float acc = __logf(prod);

    // Warp reduce, park partial, sync only this half's 256 threads via a
    // named barrier (id 1 for half 0, id 2 for half 1).
#pragma unroll
    for (int o = 16; o > 0; o >>= 1)
        acc += __shfl_xor_sync(0xffffffffu, acc, o);

    __shared__ float ssum[2][8];
    const int lane = t & 31;
    const int warp = t >> 5;                     // 0..7 within the half
    if (lane == 0) ssum[half][warp] = acc;

    asm volatile("bar.sync %0, 256;" :: "r"(half + 1) : "memory");

    if (warp == 0) {
        float s = (lane < 8) ? ssum[half][lane] : 0.0f;
#pragma unroll
        for (int o = 4; o > 0; o >>= 1)
            s += __shfl_xor_sync(0xffffffffu, s, o);
        if (lane == 0) logdet[row] = s;
    }
}

extern "C" void kernel_launch(void* const* d_in, const int* in_sizes, int n_in,
                              void* d_out, int out_size)
{
    const float* x = (const float*)d_in[0];
    const float* w = (const float*)d_in[1];
    float* out = (float*)d_out;

    const int total = in_sizes[0];          // B * F
    const int batch = out_size - total;     // out = y (B*F) ++ logdet (B)
    const int F     = total / batch;        // 3072

    float* y      = out;
    float* logdet = out + (size_t)total;

    moebius_kernel<<<batch / 2, 512>>>(x, w, y, logdet, F);
}

// round 12
// speedup vs baseline: 1.2066x; 1.0241x over previous
#include <cuda_runtime.h>
#include <math.h>

// Moebius transform on 3-D blocks + log|det J| row reduction.
// FINAL configuration — best measured across 8 structural variants
// (41.66us kernel, 6.27 TB/s = ~79% HBM spec, at the measured B300
// LTS chip ceiling for a 2:1 read:write mixed stream).
//
// One CTA per batch row (grid=8192, 256 threads); thread t handles floats
// [t*12, t*12+12) = 4 blocks of 3. All global traffic is float4; the 48B
// lane stride is merged into full lines by L2 (verified: smem-staged fully
// coalesced variant was SLOWER, 64.5% DRAM).
// y stores use evict-first (.cs): pure write stream, no reuse.
// Determinant via conformal-map closed form: the Moebius block map is
// conformal, J = c * Householder on the tangent space, so
// |det J| = c^2 * |yn . Hn|, c = (1-|w|^2)/|n+w|^2,
// Hn = n - 2 p (n.p)/|p|^2. One __logf of the product of 4 block dets
// replaces 4 softlog expansions.

__device__ __forceinline__ float fast_rcp(float a) {
    float r;
    asm("rcp.approx.f32 %0, %1;" : "=f"(r) : "f"(a));
    return r;
}

__device__ __forceinline__ float moebius_block3(
    float a0, float a1, float a2,     // x block
    float v0, float v1, float v2,     // w block
    float& y0, float& y1, float& y2)  // y block out
{
    // radial normalization
    float xns   = fmaf(a0, a0, fmaf(a1, a1, a2 * a2));
    float inv   = rsqrtf(xns);
    float xnorm = xns * inv;                 // sqrt(xns)

    float n0 = a0 * inv, n1 = a1 * inv, n2 = a2 * inv;
    float p0 = n0 + v0,  p1 = n1 + v1,  p2 = n2 + v2;   // n + w

    float wns  = fmaf(v0, v0, fmaf(v1, v1, v2 * v2));
    float pns  = fmaf(p0, p0, fmaf(p1, p1, p2 * p2));
    float invp = fast_rcp(pns);
    float c    = (1.0f - wns) * invp;

    float yn0 = fmaf(c, p0, v0);
    float yn1 = fmaf(c, p1, v1);
    float yn2 = fmaf(c, p2, v2);

    y0 = xnorm * yn0;
    y1 = xnorm * yn1;
    y2 = xnorm * yn2;

    // |det J| = c^2 * | yn . (n - 2 p (n.p)/|p|^2) |
    float np = fmaf(n0, p0, fmaf(n1, p1, n2 * p2));
    float t  = 2.0f * np * invp;
    float h0 = fmaf(-t, p0, n0);
    float h1 = fmaf(-t, p1, n1);
    float h2 = fmaf(-t, p2, n2);
    float d  = fmaf(yn0, h0, fmaf(yn1, h1, yn2 * h2));

    return c * c * fabsf(d);
}

__global__ void __launch_bounds__(256)
moebius_kernel(const float* __restrict__ x,
               const float* __restrict__ w,
               float* __restrict__ y,
               float* __restrict__ logdet,
               int F)
{
    const int row  = blockIdx.x;
    const int t    = threadIdx.x;
    const int base = row * F + t * 12;           // B*F < 2^31, fits int

    // 3x float4 loads of x and w each (12 floats = 4 blocks of 3),
    // front-batched for maximum MLP.
    const float4* xv = reinterpret_cast<const float4*>(x + base);
    const float4* wv = reinterpret_cast<const float4*>(w + base);
    float4 xa = xv[0], xb = xv[1], xc = xv[2];
    float4 wa = wv[0], wb = wv[1], wc = wv[2];

    float ys[12];
    float prod, pk;

    prod  = moebius_block3(xa.x, xa.y, xa.z, wa.x, wa.y, wa.z,
                           ys[0], ys[1], ys[2]);
    pk    = moebius_block3(xa.w, xb.x, xb.y, wa.w, wb.x, wb.y,
                           ys[3], ys[4], ys[5]);
    prod *= pk;
    pk    = moebius_block3(xb.z, xb.w, xc.x, wb.z, wb.w, wc.x,
                           ys[6], ys[7], ys[8]);
    prod *= pk;
    pk    = moebius_block3(xc.y, xc.z, xc.w, wc.y, wc.z, wc.w,
                           ys[9], ys[10], ys[11]);
    prod *= pk;

    float4* yv = reinterpret_cast<float4*>(y + base);
    __stcs(yv + 0, make_float4(ys[0], ys[1], ys[2],  ys[3]));
    __stcs(yv + 1, make_float4(ys[4], ys[5], ys[6],  ys[7]));
    __stcs(yv + 2, make_float4(ys[8], ys[9], ys[10], ys[11]));

    // log of product of the 4 |det|s: one fast log per thread
    float acc = __logf(prod);

    // Reduce acc over the CTA (one row) — warp shuffle then shared.
#pragma unroll
    for (int o = 16; o > 0; o >>= 1)
        acc += __shfl_xor_sync(0xffffffffu, acc, o);

    __shared__ float ssum[8];
    const int lane = t & 31;
    const int warp = t >> 5;
    if (lane == 0) ssum[warp] = acc;
    __syncthreads();

    if (warp == 0) {
        float s = (lane < 8) ? ssum[lane] : 0.0f;
#pragma unroll
        for (int o = 4; o > 0; o >>= 1)
            s += __shfl_xor_sync(0xffffffffu, s, o);
        if (lane == 0) logdet[row] = s;
    }
}

extern "C" void kernel_launch(void* const* d_in, const int* in_sizes, int n_in,
                              void* d_out, int out_size)
{
    const float* x = (const float*)d_in[0];
    const float* w = (const float*)d_in[1];
    float* out = (float*)d_out;

    const int total = in_sizes[0];          // B * F
    const int batch = out_size - total;     // out = y (B*F) ++ logdet (B)
    const int F     = total / batch;        // 3072

    float* y      = out;
    float* logdet = out + (size_t)total;

    const int threads = F / 12;             // 256: 4 blocks of 3 per thread
    moebius_kernel<<<batch, threads>>>(x, w, y, logdet, F);
}